// round 1
// baseline (speedup 1.0000x reference)
#include <cuda_runtime.h>
#include <math.h>
#include <stdint.h>

#define NN    65536
#define DDIM  128
#define KDIM  640      // [x(512) | h(128)]
#define NG    384      // 3*128 gates
#define BM    64       // rows per block

#define XP    644      // sX row stride (pad: 644 % 32 == 4 -> conflict-free A frags)
#define WP    388      // sW row stride
#define HP    132      // sH row stride

#define OFF_W (BM*XP)            // 41216
#define OFF_H (OFF_W + 16*WP)    // 47424
#define SMEM_FLOATS (OFF_H + BM*HP)  // 55872 floats = 223488 B

// ---------------- device scratch (static, allocation-free) ----------------
__device__ float g_WcT[2][KDIM][NG];   // [branch][k][n], tf32-rounded, Wc = [Wih | Whh]
__device__ float g_WhhnT[2][DDIM][DDIM]; // Whh_n transposed: [k][j]
__device__ float g_bc[2][NG];          // bih + bhh
__device__ float g_bhn[2][DDIM];       // bhh[256:384]

__device__ __forceinline__ float tf32r(float f) {
    unsigned u;
    asm("cvt.rna.tf32.f32 %0, %1;" : "=r"(u) : "f"(f));
    return __uint_as_float(u);
}

__device__ __forceinline__ void mma8(float c[4], const unsigned a[4], const unsigned b[2]) {
    asm volatile(
        "mma.sync.aligned.m16n8k8.row.col.f32.tf32.tf32.f32 "
        "{%0,%1,%2,%3},{%4,%5,%6,%7},{%8,%9},{%0,%1,%2,%3};"
        : "+f"(c[0]), "+f"(c[1]), "+f"(c[2]), "+f"(c[3])
        : "r"(a[0]), "r"(a[1]), "r"(a[2]), "r"(a[3]), "r"(b[0]), "r"(b[1]));
}

// ---------------- weight packing (runs every launch; deterministic) -------
__global__ void pack_kernel(const float* Wih0, const float* Whh0, const float* bih0, const float* bhh0,
                            const float* Wih1, const float* Whh1, const float* bih1, const float* bhh1) {
    const float* Wih[2] = {Wih0, Wih1};
    const float* Whh[2] = {Whh0, Whh1};
    const float* bih[2] = {bih0, bih1};
    const float* bhh[2] = {bhh0, bhh1};
    int stride = gridDim.x * blockDim.x;
    int gid = blockIdx.x * blockDim.x + threadIdx.x;

    for (int t = gid; t < 2 * KDIM * NG; t += stride) {
        int b = t / (KDIM * NG), rem = t % (KDIM * NG);
        int k = rem / NG, n = rem % NG;
        float v = (k < 512) ? Wih[b][n * 512 + k] : Whh[b][n * 128 + (k - 512)];
        g_WcT[b][k][n] = tf32r(v);
    }
    for (int t = gid; t < 2 * DDIM * DDIM; t += stride) {
        int b = t / (DDIM * DDIM), rem = t % (DDIM * DDIM);
        int k = rem / DDIM, j = rem % DDIM;
        g_WhhnT[b][k][j] = tf32r(Whh[b][(256 + j) * 128 + k]);
    }
    for (int t = gid; t < 2 * NG; t += stride) {
        int b = t / NG, n = t % NG;
        g_bc[b][n] = bih[b][n] + bhh[b][n];
    }
    for (int t = gid; t < 2 * DDIM; t += stride) {
        int b = t / DDIM, j = t % DDIM;
        g_bhn[b][j] = bhh[b][256 + j];
    }
}

// ---------------- fused TGN kernel ----------------------------------------
__global__ __launch_bounds__(256, 1)
void tgn_main(const int* __restrict__ n_id,
              const float* __restrict__ memf, const float* __restrict__ pos_mem,
              const float* __restrict__ pos_emb,
              const float* __restrict__ raw_s, const float* __restrict__ raw_d,
              const int* __restrict__ other_s, const int* __restrict__ other_d,
              const int* __restrict__ t_s, const int* __restrict__ t_d,
              const int* __restrict__ last_up,
              const float* __restrict__ wtm, const float* __restrict__ btm,
              const float* __restrict__ wtp, const float* __restrict__ btp,
              float* __restrict__ out) {
    extern __shared__ float sm[];
    float* sX = sm;           // [64][644]
    float* sW = sm + OFF_W;   // [16][388]
    float* sH = sm + OFF_H;   // [64][132]
    __shared__ int sh_nid[BM];
    __shared__ int sh_other[BM];
    __shared__ float sh_dt[BM];
    __shared__ const float* sh_feat[BM];

    const int br = blockIdx.y;
    const float* Mb = br ? pos_mem : memf;
    const float* wt = br ? wtp : wtm;
    const float* bt = br ? btp : btm;
    const int tid = threadIdx.x;
    const int row0g = blockIdx.x * BM;

    // per-row scalar prep
    if (tid < BM) {
        int i = row0g + tid;
        int nid = n_id[i];
        int os = other_s[i], od = other_d[i];
        int ts = t_s[i], td = t_d[i];
        int lu = last_up[nid];  // gathered by node id (matches reference)
        bool pick = ts >= td;
        sh_nid[tid] = nid;
        sh_other[tid] = pick ? os : od;
        sh_dt[tid] = (float)((pick ? ts : td) - lu);
        sh_feat[tid] = br ? (pick ? pos_emb + (size_t)nid * DDIM : pos_emb + (size_t)od * DDIM)
                          : (pick ? raw_s + (size_t)i * DDIM : raw_d + (size_t)i * DDIM);
        if (br == 0) out[(size_t)2 * NN * DDIM + i] = (float)(ts > td ? ts : td);
    }
    __syncthreads();

    // assemble Xfull tile [64][640] (tf32-rounded) into smem
    for (int idx = tid; idx < BM * 160; idx += 256) {
        int r = idx / 160;
        int c = (idx % 160) * 4;
        float4 v;
        if (c < 128)      v = *(const float4*)(Mb + (size_t)sh_nid[r] * DDIM + c);
        else if (c < 256) v = *(const float4*)(Mb + (size_t)sh_other[r] * DDIM + (c - 128));
        else if (c < 384) v = *(const float4*)(sh_feat[r] + (c - 256));
        else if (c < 512) {
            int j = c - 384;
            float dt = sh_dt[r];
            v.x = cosf(dt * wt[j + 0] + bt[j + 0]);
            v.y = cosf(dt * wt[j + 1] + bt[j + 1]);
            v.z = cosf(dt * wt[j + 2] + bt[j + 2]);
            v.w = cosf(dt * wt[j + 3] + bt[j + 3]);
        } else            v = *(const float4*)(Mb + (size_t)sh_nid[r] * DDIM + (c - 512));
        v.x = tf32r(v.x); v.y = tf32r(v.y); v.z = tf32r(v.z); v.w = tf32r(v.w);
        *(float4*)(sX + r * XP + c) = v;
    }
    __syncthreads();

    const int warp = tid >> 5, lane = tid & 31;
    const int g = lane >> 2, tg = lane & 3;
    const int wm = warp & 1, wn = warp >> 1;  // 2(M) x 4(N) warp grid

    // -------- stage 1: hn = h @ Whh_n^T  (64x128, K=128) --------
    {
        float hacc[2][4][4];
#pragma unroll
        for (int mt = 0; mt < 2; mt++)
#pragma unroll
            for (int nt = 0; nt < 4; nt++)
#pragma unroll
                for (int q = 0; q < 4; q++) hacc[mt][nt][q] = 0.f;

        for (int p = 0; p < 8; p++) {
            for (int idx = tid; idx < 16 * 32; idx += 256) {
                int kk = idx >> 5;
                int c = (idx & 31) * 4;
                *(float4*)(sW + kk * WP + c) = *(const float4*)(&g_WhhnT[br][p * 16 + kk][c]);
            }
            __syncthreads();
#pragma unroll
            for (int kk = 0; kk < 16; kk += 8) {
                int kc = p * 16 + kk;
                unsigned a[2][4];
#pragma unroll
                for (int mt = 0; mt < 2; mt++) {
                    int rb = wm * 32 + mt * 16;
                    a[mt][0] = __float_as_uint(sX[(rb + g) * XP + kc + tg]);
                    a[mt][1] = __float_as_uint(sX[(rb + g + 8) * XP + kc + tg]);
                    a[mt][2] = __float_as_uint(sX[(rb + g) * XP + kc + tg + 4]);
                    a[mt][3] = __float_as_uint(sX[(rb + g + 8) * XP + kc + tg + 4]);
                }
                unsigned b[4][2];
#pragma unroll
                for (int nt = 0; nt < 4; nt++) {
                    int n = wn * 32 + nt * 8 + g;
                    b[nt][0] = __float_as_uint(sW[(kk + tg) * WP + n]);
                    b[nt][1] = __float_as_uint(sW[(kk + tg + 4) * WP + n]);
                }
#pragma unroll
                for (int mt = 0; mt < 2; mt++)
#pragma unroll
                    for (int nt = 0; nt < 4; nt++) mma8(hacc[mt][nt], a[mt], b[nt]);
            }
            __syncthreads();
        }
#pragma unroll
        for (int mt = 0; mt < 2; mt++) {
            int rb = wm * 32 + mt * 16;
#pragma unroll
            for (int nt = 0; nt < 4; nt++) {
                int cb = wn * 32 + nt * 8 + tg * 2;
                sH[(rb + g) * HP + cb]     = hacc[mt][nt][0];
                sH[(rb + g) * HP + cb + 1] = hacc[mt][nt][1];
                sH[(rb + g + 8) * HP + cb]     = hacc[mt][nt][2];
                sH[(rb + g + 8) * HP + cb + 1] = hacc[mt][nt][3];
            }
        }
    }
    __syncthreads();

    // -------- stage 2: G = Xfull @ Wc^T  (64x384, K=640) --------
    float acc[2][12][4];
#pragma unroll
    for (int mt = 0; mt < 2; mt++)
#pragma unroll
        for (int nt = 0; nt < 12; nt++)
#pragma unroll
            for (int q = 0; q < 4; q++) acc[mt][nt][q] = 0.f;

    for (int p = 0; p < 40; p++) {
        for (int idx = tid; idx < 16 * 96; idx += 256) {
            int kk = idx / 96;
            int c = (idx % 96) * 4;
            *(float4*)(sW + kk * WP + c) = *(const float4*)(&g_WcT[br][p * 16 + kk][c]);
        }
        __syncthreads();
#pragma unroll
        for (int kk = 0; kk < 16; kk += 8) {
            int kc = p * 16 + kk;
            unsigned a[2][4];
#pragma unroll
            for (int mt = 0; mt < 2; mt++) {
                int rb = wm * 32 + mt * 16;
                a[mt][0] = __float_as_uint(sX[(rb + g) * XP + kc + tg]);
                a[mt][1] = __float_as_uint(sX[(rb + g + 8) * XP + kc + tg]);
                a[mt][2] = __float_as_uint(sX[(rb + g) * XP + kc + tg + 4]);
                a[mt][3] = __float_as_uint(sX[(rb + g + 8) * XP + kc + tg + 4]);
            }
            unsigned b[12][2];
#pragma unroll
            for (int nt = 0; nt < 12; nt++) {
                int n = wn * 96 + nt * 8 + g;
                b[nt][0] = __float_as_uint(sW[(kk + tg) * WP + n]);
                b[nt][1] = __float_as_uint(sW[(kk + tg + 4) * WP + n]);
            }
#pragma unroll
            for (int mt = 0; mt < 2; mt++)
#pragma unroll
                for (int nt = 0; nt < 12; nt++) mma8(acc[mt][nt], a[mt], b[nt]);
        }
        __syncthreads();
    }

    // -------- epilogue: stage G through sX cols [256,640), apply gates -----
#pragma unroll
    for (int mt = 0; mt < 2; mt++) {
        int rb = wm * 32 + mt * 16;
#pragma unroll
        for (int nt = 0; nt < 12; nt++) {
            int cb = 256 + wn * 96 + nt * 8 + tg * 2;
            sX[(rb + g) * XP + cb]     = acc[mt][nt][0];
            sX[(rb + g) * XP + cb + 1] = acc[mt][nt][1];
            sX[(rb + g + 8) * XP + cb]     = acc[mt][nt][2];
            sX[(rb + g + 8) * XP + cb + 1] = acc[mt][nt][3];
        }
    }
    __syncthreads();

    for (int idx = tid; idx < BM * 32; idx += 256) {
        int r = idx >> 5;
        int j0 = (idx & 31) * 4;
        int i = row0g + r;
        const float* hrow = Mb + (size_t)sh_nid[r] * DDIM;  // exact fp32 h
        float* orow = out + (size_t)br * NN * DDIM + (size_t)i * DDIM;
#pragma unroll
        for (int u = 0; u < 4; u++) {
            int j = j0 + u;
            float Gr = sX[r * XP + 256 + j]       + g_bc[br][j];
            float Gz = sX[r * XP + 256 + 128 + j] + g_bc[br][128 + j];
            float Gn = sX[r * XP + 256 + 256 + j] + g_bc[br][256 + j];
            float hn = sH[r * HP + j] + g_bhn[br][j];
            float rr = 1.f / (1.f + expf(-Gr));
            float zz = 1.f / (1.f + expf(-Gz));
            float nn = tanhf(Gn + (rr - 1.f) * hn);  // inn + r*hn == Gn + (r-1)*hn
            float h = hrow[j];
            orow[j] = (1.f - zz) * nn + zz * h;
        }
    }
}

// ---------------- launch ----------------------------------------------------
extern "C" void kernel_launch(void* const* d_in, const int* in_sizes, int n_in,
                              void* d_out, int out_size) {
    const int*   n_id    = (const int*)d_in[0];
    const float* memory  = (const float*)d_in[1];
    const float* pos_mem = (const float*)d_in[2];
    const float* pos_emb = (const float*)d_in[3];
    const float* raw_s   = (const float*)d_in[4];
    const float* raw_d   = (const float*)d_in[5];
    const int*   other_s = (const int*)d_in[6];
    const int*   other_d = (const int*)d_in[7];
    const int*   t_s     = (const int*)d_in[8];
    const int*   t_d     = (const int*)d_in[9];
    const int*   last_up = (const int*)d_in[10];
    const float* wtm = (const float*)d_in[11];
    const float* btm = (const float*)d_in[12];
    const float* wtp = (const float*)d_in[13];
    const float* btp = (const float*)d_in[14];
    const float* Wih_m = (const float*)d_in[15];
    const float* Whh_m = (const float*)d_in[16];
    const float* bih_m = (const float*)d_in[17];
    const float* bhh_m = (const float*)d_in[18];
    const float* Wih_p = (const float*)d_in[19];
    const float* Whh_p = (const float*)d_in[20];
    const float* bih_p = (const float*)d_in[21];
    const float* bhh_p = (const float*)d_in[22];
    float* out = (float*)d_out;

    pack_kernel<<<512, 256>>>(Wih_m, Whh_m, bih_m, bhh_m, Wih_p, Whh_p, bih_p, bhh_p);

    const int smem_bytes = SMEM_FLOATS * 4;  // 223488
    cudaFuncSetAttribute(tgn_main, cudaFuncAttributeMaxDynamicSharedMemorySize, smem_bytes);
    dim3 grid(NN / BM, 2);
    tgn_main<<<grid, 256, smem_bytes>>>(n_id, memory, pos_mem, pos_emb, raw_s, raw_d,
                                        other_s, other_d, t_s, t_d, last_up,
                                        wtm, btm, wtp, btp, out);
}